// round 1
// baseline (speedup 1.0000x reference)
#include <cuda_runtime.h>
#include <math.h>

// ---------------------------------------------------------------------------
// HSGNN forward, GB300.
// Inputs (metadata order):
//   0 features [5000,512] f32
//   1 adj      [3,5000,5000] f32 (binary)
//   2 W_gnn    [3,512,16] f32
//   3 b_gnn    [3,16] f32
//   4 att_w    [3,32,1] f32
//   5 W_final  [16,100] f32
//   6 b_final  [100] f32
// Output: concat(f_meta[5000,16], A_meta[5000,5000], predictions[5000,100])
// ---------------------------------------------------------------------------

#define NN 5000
#define WPR 157      // ceil(5000/32) words per bitmask row
#define WPRP 160     // padded words per row
#define DOUT 16
#define NCLS 100

__device__ unsigned g_bits[3][NN * WPRP];   // per-meta-path adjacency bitmasks
__device__ unsigned g_union[NN * WPRP];     // union pattern
__device__ float    g_dinv[3][NN];          // D^{-1/2} per meta-path (incl. self loop)
__device__ float    g_dinvu[NN];            // D^{-1/2} for union pattern
__device__ float    g_XW[3][NN * DOUT];     // features @ W_gnn
__device__ float    g_atta[NN * 4];         // a[i,k] (padded stride 4)
__device__ float    g_attb[NN * 4];         // b[j,k]
__device__ float    g_t[NN * DOUT];         // norm_meta @ f_meta

// ---------------------------------------------------------------------------
// K1: stream adj (300 MB) once -> bitmasks + degrees.
// Block per (k,i) row; 8 warps; each warp builds 4 words per iteration
// (4 independent 128B loads in flight before the dependent ballots).
// ---------------------------------------------------------------------------
__global__ void k_bits(const float* __restrict__ adj) {
    int b = blockIdx.x;                 // b = k*NN + i
    int k = b / NN, i = b - k * NN;
    const float* row = adj + (size_t)b * NN;
    int lane = threadIdx.x & 31, warp = threadIdx.x >> 5;   // 8 warps
    __shared__ int s_cnt;
    if (threadIdx.x == 0) s_cnt = 0;
    __syncthreads();
    int local = 0;
    #pragma unroll
    for (int it = 0; it < 5; it++) {
        int w0 = it * 32 + warp * 4;
        int w1 = w0 + 1, w2 = w0 + 2, w3 = w0 + 3;
        float v0 = 0.f, v1 = 0.f, v2 = 0.f, v3 = 0.f;
        if (w0 < WPR) { int j = w0 * 32 + lane; v0 = (j < NN) ? row[j] : 0.f; }
        if (w1 < WPR) { int j = w1 * 32 + lane; v1 = (j < NN) ? row[j] : 0.f; }
        if (w2 < WPR) { int j = w2 * 32 + lane; v2 = (j < NN) ? row[j] : 0.f; }
        if (w3 < WPR) { int j = w3 * 32 + lane; v3 = (j < NN) ? row[j] : 0.f; }
        unsigned m0 = __ballot_sync(0xffffffffu, v0 != 0.f);
        unsigned m1 = __ballot_sync(0xffffffffu, v1 != 0.f);
        unsigned m2 = __ballot_sync(0xffffffffu, v2 != 0.f);
        unsigned m3 = __ballot_sync(0xffffffffu, v3 != 0.f);
        if (lane == 0) {
            unsigned* bp = &g_bits[k][i * WPRP];
            if (w0 < WPR) { bp[w0] = m0; local += __popc(m0); }
            if (w1 < WPR) { bp[w1] = m1; local += __popc(m1); }
            if (w2 < WPR) { bp[w2] = m2; local += __popc(m2); }
            if (w3 < WPR) { bp[w3] = m3; local += __popc(m3); }
        }
    }
    if (lane == 0 && local) atomicAdd(&s_cnt, local);
    __syncthreads();
    if (threadIdx.x == 0) g_dinv[k][i] = rsqrtf((float)(s_cnt + 1));
}

// ---------------------------------------------------------------------------
// K2: union pattern + union degrees (all L2-resident reads)
// ---------------------------------------------------------------------------
__global__ void k_union() {
    int i = blockIdx.x;
    int t = threadIdx.x;                // 192 threads
    __shared__ int s_cnt;
    if (t == 0) s_cnt = 0;
    __syncthreads();
    if (t < WPR) {
        unsigned u = g_bits[0][i * WPRP + t] | g_bits[1][i * WPRP + t] |
                     g_bits[2][i * WPRP + t];
        g_union[i * WPRP + t] = u;
        int p = __popc(u);
        if (p) atomicAdd(&s_cnt, p);
    }
    __syncthreads();
    if (t == 0) g_dinvu[i] = rsqrtf((float)(s_cnt + 1));
}

// ---------------------------------------------------------------------------
// K3: XW[k] = features @ W_gnn[k]   (8 rows per block, smem-staged features)
// ---------------------------------------------------------------------------
__global__ void k_xw(const float* __restrict__ feat, const float* __restrict__ W) {
    __shared__ float sf[8 * 512];
    int i0 = blockIdx.x * 8;
    for (int idx = threadIdx.x; idx < 8 * 512; idx += blockDim.x)
        sf[idx] = feat[(size_t)i0 * 512 + idx];
    __syncthreads();
    for (int oidx = threadIdx.x; oidx < 8 * 48; oidx += blockDim.x) {
        int r = oidx / 48, rem = oidx - r * 48;
        int k = rem >> 4, o = rem & 15;
        const float* wp = W + k * 512 * 16 + o;
        const float* fp = sf + r * 512;
        float acc = 0.f;
        #pragma unroll 8
        for (int d = 0; d < 512; d++) acc = fmaf(fp[d], wp[d * 16], acc);
        g_XW[k][(i0 + r) * DOUT + o] = acc;
    }
}

#define ACC16(dj, ptr) do {                                                   \
    const float4* _x = (const float4*)(ptr);                                  \
    float4 _a = _x[0], _b = _x[1], _c = _x[2], _d = _x[3];                    \
    acc[0]  = fmaf((dj), _a.x, acc[0]);  acc[1]  = fmaf((dj), _a.y, acc[1]);  \
    acc[2]  = fmaf((dj), _a.z, acc[2]);  acc[3]  = fmaf((dj), _a.w, acc[3]);  \
    acc[4]  = fmaf((dj), _b.x, acc[4]);  acc[5]  = fmaf((dj), _b.y, acc[5]);  \
    acc[6]  = fmaf((dj), _b.z, acc[6]);  acc[7]  = fmaf((dj), _b.w, acc[7]);  \
    acc[8]  = fmaf((dj), _c.x, acc[8]);  acc[9]  = fmaf((dj), _c.y, acc[9]);  \
    acc[10] = fmaf((dj), _c.z, acc[10]); acc[11] = fmaf((dj), _c.w, acc[11]); \
    acc[12] = fmaf((dj), _d.x, acc[12]); acc[13] = fmaf((dj), _d.y, acc[13]); \
    acc[14] = fmaf((dj), _d.z, acc[14]); acc[15] = fmaf((dj), _d.w, acc[15]); \
} while (0)

// ---------------------------------------------------------------------------
// K4: per-meta-path GCN conv (bitmask SpMM, 16 dims) + max over k -> f_meta
// One warp per row.
// ---------------------------------------------------------------------------
__global__ void k_h(const float* __restrict__ bgnn, float* __restrict__ fmeta) {
    int gw = (blockIdx.x * blockDim.x + threadIdx.x) >> 5;
    int lane = threadIdx.x & 31;
    if (gw >= NN) return;
    int i = gw;
    float best[16];
    #pragma unroll
    for (int o = 0; o < 16; o++) best[o] = -3.402823e38f;

    for (int k = 0; k < 3; k++) {
        float acc[16];
        #pragma unroll
        for (int o = 0; o < 16; o++) acc[o] = 0.f;
        const unsigned* bw = &g_bits[k][i * WPRP];
        const float* dv = g_dinv[k];
        const float* X = g_XW[k];
        for (int w = lane; w < WPR; w += 32) {
            unsigned m = bw[w];
            while (m) {
                int bpos = __ffs(m) - 1; m &= m - 1;
                int j = w * 32 + bpos;
                float dj = dv[j];
                ACC16(dj, X + j * DOUT);
            }
        }
        #pragma unroll
        for (int o = 0; o < 16; o++) {
            #pragma unroll
            for (int off = 16; off >= 1; off >>= 1)
                acc[o] += __shfl_xor_sync(0xffffffffu, acc[o], off);
        }
        float di = dv[i];
        #pragma unroll
        for (int o = 0; o < 16; o++) {
            float h = di * (acc[o] + di * X[i * DOUT + o]) + bgnn[k * 16 + o];
            best[o] = fmaxf(best[o], h);
        }
    }
    if (lane == 0) {
        float4* out = (float4*)(fmeta + i * DOUT);
        out[0] = make_float4(best[0], best[1], best[2], best[3]);
        out[1] = make_float4(best[4], best[5], best[6], best[7]);
        out[2] = make_float4(best[8], best[9], best[10], best[11]);
        out[3] = make_float4(best[12], best[13], best[14], best[15]);
    }
}

// ---------------------------------------------------------------------------
// K5: attention projections a[i,k], b[i,k]
// ---------------------------------------------------------------------------
__global__ void k_att(const float* __restrict__ attw, const float* __restrict__ fmeta) {
    int i = blockIdx.x * blockDim.x + threadIdx.x;
    if (i >= NN) return;
    float f[16];
    #pragma unroll
    for (int o = 0; o < 16; o++) f[o] = fmeta[i * DOUT + o];
    #pragma unroll
    for (int k = 0; k < 3; k++) {
        float a = 0.f, b = 0.f;
        #pragma unroll
        for (int o = 0; o < 16; o++) {
            a = fmaf(f[o], attw[k * 32 + o], a);
            b = fmaf(f[o], attw[k * 32 + 16 + o], b);
        }
        g_atta[i * 4 + k] = a;
        g_attb[i * 4 + k] = b;
    }
}

// ---------------------------------------------------------------------------
// K6: A_meta dense write (100 MB). One float4 (4 columns) per thread.
// attn computed only on union-nonzero entries; else zero.
// ---------------------------------------------------------------------------
__global__ void k_ameta(float* __restrict__ Am) {
    int tid = blockIdx.x * blockDim.x + threadIdx.x;
    if (tid >= NN * 1250) return;
    int i = tid / 1250, q = tid - i * 1250;
    int j0 = q * 4, w = j0 >> 5, sh = j0 & 31;
    unsigned uw = g_union[i * WPRP + w];
    float4 out = make_float4(0.f, 0.f, 0.f, 0.f);
    unsigned sub = (uw >> sh) & 0xFu;
    if (sub) {
        float a0 = g_atta[i * 4 + 0];
        float a1 = g_atta[i * 4 + 1];
        float a2 = g_atta[i * 4 + 2];
        unsigned m0 = g_bits[0][i * WPRP + w] >> sh;
        unsigned m1 = g_bits[1][i * WPRP + w] >> sh;
        unsigned m2 = g_bits[2][i * WPRP + w] >> sh;
        float v[4];
        #pragma unroll
        for (int t = 0; t < 4; t++) {
            float r = 0.f;
            if ((sub >> t) & 1u) {
                int j = j0 + t;
                float s0 = expf(fmaxf(a0 + g_attb[j * 4 + 0], 0.f));
                float s1 = expf(fmaxf(a1 + g_attb[j * 4 + 1], 0.f));
                float s2 = expf(fmaxf(a2 + g_attb[j * 4 + 2], 0.f));
                float num = (((m0 >> t) & 1u) ? s0 : 0.f) +
                            (((m1 >> t) & 1u) ? s1 : 0.f) +
                            (((m2 >> t) & 1u) ? s2 : 0.f);
                r = num / (s0 + s1 + s2);
            }
            v[t] = r;
        }
        out = make_float4(v[0], v[1], v[2], v[3]);
    }
    ((float4*)Am)[tid] = out;
}

// ---------------------------------------------------------------------------
// K7: t = norm_meta @ f_meta  (union bitmask SpMM, 16 dims). Warp per row.
// ---------------------------------------------------------------------------
__global__ void k_tmeta(const float* __restrict__ fmeta) {
    int gw = (blockIdx.x * blockDim.x + threadIdx.x) >> 5;
    int lane = threadIdx.x & 31;
    if (gw >= NN) return;
    int i = gw;
    float acc[16];
    #pragma unroll
    for (int o = 0; o < 16; o++) acc[o] = 0.f;
    const unsigned* bw = g_union + i * WPRP;
    for (int w = lane; w < WPR; w += 32) {
        unsigned m = bw[w];
        while (m) {
            int bpos = __ffs(m) - 1; m &= m - 1;
            int j = w * 32 + bpos;
            float dj = g_dinvu[j];
            ACC16(dj, fmeta + j * DOUT);
        }
    }
    #pragma unroll
    for (int o = 0; o < 16; o++) {
        #pragma unroll
        for (int off = 16; off >= 1; off >>= 1)
            acc[o] += __shfl_xor_sync(0xffffffffu, acc[o], off);
    }
    float di = g_dinvu[i];
    if (lane == 0) {
        float r[16];
        #pragma unroll
        for (int o = 0; o < 16; o++)
            r[o] = di * (acc[o] + di * fmeta[i * DOUT + o]);
        float4* out = (float4*)(g_t + i * DOUT);
        out[0] = make_float4(r[0], r[1], r[2], r[3]);
        out[1] = make_float4(r[4], r[5], r[6], r[7]);
        out[2] = make_float4(r[8], r[9], r[10], r[11]);
        out[3] = make_float4(r[12], r[13], r[14], r[15]);
    }
}

// ---------------------------------------------------------------------------
// K8: predictions = t @ W_final + b_final   [5000,16]x[16,100]
// ---------------------------------------------------------------------------
__global__ void k_pred(const float* __restrict__ Wf, const float* __restrict__ bf,
                       float* __restrict__ out) {
    int tid = blockIdx.x * blockDim.x + threadIdx.x;
    if (tid >= NN * NCLS) return;
    int i = tid / NCLS, c = tid - i * NCLS;
    float acc = bf[c];
    #pragma unroll
    for (int o = 0; o < 16; o++)
        acc = fmaf(g_t[i * DOUT + o], Wf[o * NCLS + c], acc);
    out[tid] = acc;
}

// ---------------------------------------------------------------------------
extern "C" void kernel_launch(void* const* d_in, const int* in_sizes, int n_in,
                              void* d_out, int out_size) {
    const float* features = (const float*)d_in[0];
    const float* adj      = (const float*)d_in[1];
    const float* W_gnn    = (const float*)d_in[2];
    const float* b_gnn    = (const float*)d_in[3];
    const float* att_w    = (const float*)d_in[4];
    const float* W_final  = (const float*)d_in[5];
    const float* b_final  = (const float*)d_in[6];

    float* out   = (float*)d_out;
    float* fmeta = out;                                   // [5000,16]
    float* Ameta = out + (size_t)NN * DOUT;               // [5000,5000]
    float* pred  = out + (size_t)NN * DOUT + (size_t)NN * NN;  // [5000,100]

    k_bits<<<3 * NN, 256>>>(adj);
    k_union<<<NN, 192>>>();
    k_xw<<<NN / 8, 128>>>(features, W_gnn);
    k_h<<<(NN * 32 + 255) / 256, 256>>>(b_gnn, fmeta);
    k_att<<<(NN + 255) / 256, 256>>>(att_w, fmeta);
    k_ameta<<<(NN * 1250 + 255) / 256, 256>>>(Ameta);
    k_tmeta<<<(NN * 32 + 255) / 256, 256>>>(fmeta);
    k_pred<<<(NN * NCLS + 255) / 256, 256>>>(W_final, b_final, pred);
}

// round 2
// speedup vs baseline: 1.4818x; 1.4818x over previous
#include <cuda_runtime.h>
#include <math.h>

// ---------------------------------------------------------------------------
// HSGNN forward, GB300.  Sparse-bitmask pipeline, 5 kernels.
// ---------------------------------------------------------------------------

#define NN 5000
#define WPR 157      // ceil(5000/32) words per bitmask row
#define WPRP 160     // padded words per row
#define DOUT 16
#define NCLS 100

__device__ unsigned g_bits[3][NN * WPRP];   // per-meta-path adjacency bitmasks
__device__ unsigned g_union[NN * WPRP];     // union pattern
__device__ float    g_dinv[3][NN];          // D^{-1/2} per meta-path (incl. self loop)
__device__ float    g_dinvu[NN];            // D^{-1/2} for union pattern
__device__ float    g_XW[3][NN * DOUT];     // features @ W_gnn
__device__ float    g_atta[NN * 4];         // a[i,k] (padded stride 4)
__device__ float    g_attb[NN * 4];         // b[j,k]

// ---------------------------------------------------------------------------
// K1: one streaming pass over adj (300 MB) -> bitmasks (3), union, degrees.
// Block per row i; reads 3 rows (one per meta-path) as float4 with __ldcs.
// ---------------------------------------------------------------------------
__global__ void k_prep(const float* __restrict__ adj) {
    int i = blockIdx.x;
    int t = threadIdx.x;                       // 256 threads
    __shared__ unsigned s_b[3][WPRP];
    __shared__ int s_cnt[4];
    if (t < 4) s_cnt[t] = 0;
    for (int x = t; x < 3 * WPRP; x += 256) ((unsigned*)s_b)[x] = 0;
    __syncthreads();

    #pragma unroll
    for (int k = 0; k < 3; k++) {
        const float4* rp = (const float4*)(adj + ((size_t)k * NN + i) * NN);
        float4 v[5];
        #pragma unroll
        for (int u = 0; u < 5; u++) {
            int q = t + 256 * u;
            if (q < 1250) v[u] = __ldcs(rp + q);
            else          v[u] = make_float4(0.f, 0.f, 0.f, 0.f);
        }
        #pragma unroll
        for (int u = 0; u < 5; u++) {
            int q = t + 256 * u;
            unsigned nb = (v[u].x != 0.f ? 1u : 0u) | (v[u].y != 0.f ? 2u : 0u) |
                          (v[u].z != 0.f ? 4u : 0u) | (v[u].w != 0.f ? 8u : 0u);
            if (nb && q < 1250) atomicOr(&s_b[k][q >> 3], nb << ((q & 7) * 4));
        }
    }
    __syncthreads();

    if (t < WPR) {
        unsigned b0 = s_b[0][t], b1 = s_b[1][t], b2 = s_b[2][t];
        unsigned u = b0 | b1 | b2;
        g_bits[0][i * WPRP + t] = b0;
        g_bits[1][i * WPRP + t] = b1;
        g_bits[2][i * WPRP + t] = b2;
        g_union[i * WPRP + t] = u;
        if (b0) atomicAdd(&s_cnt[0], __popc(b0));
        if (b1) atomicAdd(&s_cnt[1], __popc(b1));
        if (b2) atomicAdd(&s_cnt[2], __popc(b2));
        if (u)  atomicAdd(&s_cnt[3], __popc(u));
    }
    __syncthreads();
    if (t == 0) {
        g_dinv[0][i] = rsqrtf((float)(s_cnt[0] + 1));
        g_dinv[1][i] = rsqrtf((float)(s_cnt[1] + 1));
        g_dinv[2][i] = rsqrtf((float)(s_cnt[2] + 1));
        g_dinvu[i]   = rsqrtf((float)(s_cnt[3] + 1));
    }
}

// ---------------------------------------------------------------------------
// K2: XW[k] = features @ W_gnn[k].  Register tile: 4 rows per thread share
// each W load; features staged in smem, read as float4.
// Block: 192 threads = (rq:4) x (k:3) x (o:16); 16 rows/block, grid 313.
// ---------------------------------------------------------------------------
__global__ void k_xw(const float* __restrict__ feat, const float* __restrict__ W) {
    __shared__ float sf[16 * 512];             // 32 KB
    int i0 = blockIdx.x * 16;
    for (int x = threadIdx.x; x < 16 * 128; x += 192) {
        int r = x >> 7, c = x & 127;
        int gi = i0 + r;
        float4 v = make_float4(0.f, 0.f, 0.f, 0.f);
        if (gi < NN) v = ((const float4*)feat)[(size_t)gi * 128 + c];
        ((float4*)sf)[x] = v;
    }
    __syncthreads();

    int t = threadIdx.x;
    int o = t & 15;
    int k = (t >> 4) % 3;
    int rq = t / 48;                           // 0..3
    const float* wp = W + k * (512 * 16) + o;
    const float* f0 = sf + (rq * 4 + 0) * 512;
    const float* f1 = f0 + 512;
    const float* f2 = f1 + 512;
    const float* f3 = f2 + 512;
    float a0 = 0.f, a1 = 0.f, a2 = 0.f, a3 = 0.f;
    #pragma unroll 4
    for (int d = 0; d < 512; d += 4) {
        float w0 = wp[(d + 0) * 16];
        float w1 = wp[(d + 1) * 16];
        float w2 = wp[(d + 2) * 16];
        float w3 = wp[(d + 3) * 16];
        float4 x0 = *(const float4*)(f0 + d);
        float4 x1 = *(const float4*)(f1 + d);
        float4 x2 = *(const float4*)(f2 + d);
        float4 x3 = *(const float4*)(f3 + d);
        a0 = fmaf(x0.x, w0, fmaf(x0.y, w1, fmaf(x0.z, w2, fmaf(x0.w, w3, a0))));
        a1 = fmaf(x1.x, w0, fmaf(x1.y, w1, fmaf(x1.z, w2, fmaf(x1.w, w3, a1))));
        a2 = fmaf(x2.x, w0, fmaf(x2.y, w1, fmaf(x2.z, w2, fmaf(x2.w, w3, a2))));
        a3 = fmaf(x3.x, w0, fmaf(x3.y, w1, fmaf(x3.z, w2, fmaf(x3.w, w3, a3))));
    }
    int gi = i0 + rq * 4;
    if (gi + 0 < NN) g_XW[k][(gi + 0) * DOUT + o] = a0;
    if (gi + 1 < NN) g_XW[k][(gi + 1) * DOUT + o] = a1;
    if (gi + 2 < NN) g_XW[k][(gi + 2) * DOUT + o] = a2;
    if (gi + 3 < NN) g_XW[k][(gi + 3) * DOUT + o] = a3;
}

// ---------------------------------------------------------------------------
// Deterministic nonzero-list build: word counts -> warp exclusive scan ->
// emit indices at fixed offsets. Used by k_hatt / k_tpred.
// s_w[WPRP] caches words, s_base[WPRP] offsets. Returns total via s_n.
// ---------------------------------------------------------------------------
#define BUILD_LIST(SRC)                                                       \
    do {                                                                      \
        for (int w = t; w < WPRP; w += 128) {                                 \
            unsigned m = (w < WPR) ? (SRC)[w] : 0u;                           \
            s_w[w] = m;                                                       \
            s_cntw[w] = __popc(m);                                            \
        }                                                                     \
        __syncthreads();                                                      \
        if (t < 32) {                                                         \
            int run = 0;                                                      \
            _Pragma("unroll")                                                 \
            for (int g = 0; g < 5; g++) {                                     \
                int w = g * 32 + t;                                           \
                int c = s_cntw[w];                                            \
                int x = c;                                                    \
                _Pragma("unroll")                                             \
                for (int off = 1; off < 32; off <<= 1) {                      \
                    int y = __shfl_up_sync(0xffffffffu, x, off);              \
                    if (t >= off) x += y;                                     \
                }                                                             \
                s_base[w] = run + x - c;                                      \
                run += __shfl_sync(0xffffffffu, x, 31);                       \
            }                                                                 \
            if (t == 0) s_n = run;                                            \
        }                                                                     \
        __syncthreads();                                                      \
        for (int w = t; w < WPR; w += 128) {                                  \
            unsigned m = s_w[w];                                              \
            int base = s_base[w];                                             \
            int jb = w * 32;                                                  \
            while (m) {                                                       \
                int b = __ffs(m) - 1; m &= m - 1;                             \
                s_list[base++] = jb + b;                                      \
            }                                                                 \
        }                                                                     \
        __syncthreads();                                                      \
    } while (0)

// ---------------------------------------------------------------------------
// K3: per-meta-path GCN conv + max over k -> f_meta, + attention projections.
// Block per row, 128 threads = (sub:8) x (dim:16).
// ---------------------------------------------------------------------------
__global__ void k_hatt(const float* __restrict__ bgnn, const float* __restrict__ attw,
                       float* __restrict__ fmeta) {
    int i = blockIdx.x;
    int t = threadIdx.x;
    int lane = t & 31, warp = t >> 5;
    int dim = t & 15, sub = t >> 4;
    __shared__ int s_n;
    __shared__ unsigned s_w[WPRP];
    __shared__ int s_cntw[WPRP];
    __shared__ int s_base[WPRP];
    __shared__ int s_list[320];
    __shared__ float s_part[4][16];
    __shared__ float s_best[16];

    for (int k = 0; k < 3; k++) {
        BUILD_LIST(&g_bits[k][i * WPRP]);
        int E = s_n;
        const float* X = g_XW[k];
        const float* dv = g_dinv[k];
        float acc = 0.f;
        for (int e = sub; e < E; e += 8) {
            int j = s_list[e];
            acc = fmaf(dv[j], X[j * DOUT + dim], acc);
        }
        acc += __shfl_xor_sync(0xffffffffu, acc, 16);
        if (lane < 16) s_part[warp][lane] = acc;
        __syncthreads();
        if (t < 16) {
            float s = s_part[0][t] + s_part[1][t] + s_part[2][t] + s_part[3][t];
            float di = dv[i];
            float h = fmaf(di, fmaf(di, X[i * DOUT + t], s), bgnn[k * 16 + t]);
            s_best[t] = (k == 0) ? h : fmaxf(s_best[t], h);
        }
        __syncthreads();
    }

    if (t < 32) {
        float best = (t < 16) ? s_best[t] : 0.f;
        if (t < 16) fmeta[i * DOUT + t] = best;
        #pragma unroll
        for (int k = 0; k < 3; k++) {
            float va = (t < 16) ? best * attw[k * 32 + t] : 0.f;
            float vb = (t < 16) ? best * attw[k * 32 + 16 + t] : 0.f;
            #pragma unroll
            for (int off = 8; off >= 1; off >>= 1) {
                va += __shfl_xor_sync(0xffffffffu, va, off);
                vb += __shfl_xor_sync(0xffffffffu, vb, off);
            }
            if (t == 0) { g_atta[i * 4 + k] = va; g_attb[i * 4 + k] = vb; }
        }
    }
}

// ---------------------------------------------------------------------------
// K4: A_meta dense write (100 MB), fused attention softmax on union nonzeros.
// ---------------------------------------------------------------------------
__global__ void k_ameta(float* __restrict__ Am) {
    int tid = blockIdx.x * blockDim.x + threadIdx.x;
    if (tid >= NN * 1250) return;
    int i = tid / 1250, q = tid - i * 1250;
    int j0 = q * 4, w = j0 >> 5, sh = j0 & 31;
    unsigned uw = g_union[i * WPRP + w];
    float4 out = make_float4(0.f, 0.f, 0.f, 0.f);
    unsigned sub = (uw >> sh) & 0xFu;
    if (sub) {
        float4 A = *(const float4*)&g_atta[i * 4];
        unsigned m0 = g_bits[0][i * WPRP + w] >> sh;
        unsigned m1 = g_bits[1][i * WPRP + w] >> sh;
        unsigned m2 = g_bits[2][i * WPRP + w] >> sh;
        float v[4];
        #pragma unroll
        for (int c = 0; c < 4; c++) {
            float r = 0.f;
            if ((sub >> c) & 1u) {
                int j = j0 + c;
                float4 B = *(const float4*)&g_attb[j * 4];
                float s0 = __expf(fmaxf(A.x + B.x, 0.f));
                float s1 = __expf(fmaxf(A.y + B.y, 0.f));
                float s2 = __expf(fmaxf(A.z + B.z, 0.f));
                float num = (((m0 >> c) & 1u) ? s0 : 0.f) +
                            (((m1 >> c) & 1u) ? s1 : 0.f) +
                            (((m2 >> c) & 1u) ? s2 : 0.f);
                r = __fdividef(num, s0 + s1 + s2);
            }
            v[c] = r;
        }
        out = make_float4(v[0], v[1], v[2], v[3]);
    }
    ((float4*)Am)[tid] = out;
}

// ---------------------------------------------------------------------------
// K5: t = norm_meta @ f_meta (union SpMM) fused with predictions = t@Wf + bf.
// Block per row, 128 threads.
// ---------------------------------------------------------------------------
__global__ void k_tpred(const float* __restrict__ fmeta, const float* __restrict__ Wf,
                        const float* __restrict__ bf, float* __restrict__ pred) {
    int i = blockIdx.x;
    int t = threadIdx.x;
    int lane = t & 31, warp = t >> 5;
    int dim = t & 15, sub = t >> 4;
    __shared__ int s_n;
    __shared__ unsigned s_w[WPRP];
    __shared__ int s_cntw[WPRP];
    __shared__ int s_base[WPRP];
    __shared__ int s_list[384];
    __shared__ float s_part[4][16];
    __shared__ float s_t[16];

    BUILD_LIST(&g_union[i * WPRP]);
    int E = s_n;
    float acc = 0.f;
    for (int e = sub; e < E; e += 8) {
        int j = s_list[e];
        acc = fmaf(g_dinvu[j], fmeta[j * DOUT + dim], acc);
    }
    acc += __shfl_xor_sync(0xffffffffu, acc, 16);
    if (lane < 16) s_part[warp][lane] = acc;
    __syncthreads();
    if (t < 16) {
        float s = s_part[0][t] + s_part[1][t] + s_part[2][t] + s_part[3][t];
        float di = g_dinvu[i];
        s_t[t] = di * fmaf(di, fmeta[i * DOUT + t], s);
    }
    __syncthreads();
    if (t < NCLS) {
        float p = bf[t];
        #pragma unroll
        for (int o = 0; o < DOUT; o++)
            p = fmaf(s_t[o], Wf[o * NCLS + t], p);
        pred[i * NCLS + t] = p;
    }
}

// ---------------------------------------------------------------------------
extern "C" void kernel_launch(void* const* d_in, const int* in_sizes, int n_in,
                              void* d_out, int out_size) {
    const float* features = (const float*)d_in[0];
    const float* adj      = (const float*)d_in[1];
    const float* W_gnn    = (const float*)d_in[2];
    const float* b_gnn    = (const float*)d_in[3];
    const float* att_w    = (const float*)d_in[4];
    const float* W_final  = (const float*)d_in[5];
    const float* b_final  = (const float*)d_in[6];

    float* out   = (float*)d_out;
    float* fmeta = out;                                        // [5000,16]
    float* Ameta = out + (size_t)NN * DOUT;                    // [5000,5000]
    float* pred  = out + (size_t)NN * DOUT + (size_t)NN * NN;  // [5000,100]

    k_prep<<<NN, 256>>>(adj);
    k_xw<<<(NN + 15) / 16, 192>>>(features, W_gnn);
    k_hatt<<<NN, 128>>>(b_gnn, att_w, fmeta);
    k_tpred<<<NN, 128>>>(fmeta, W_final, b_final, pred);
    k_ameta<<<(NN * 1250 + 255) / 256, 256>>>(Ameta);
}

// round 3
// speedup vs baseline: 1.7305x; 1.1678x over previous
#include <cuda_runtime.h>
#include <math.h>

// ---------------------------------------------------------------------------
// HSGNN forward, GB300.  Sparse-bitmask pipeline, 5 kernels.
// ---------------------------------------------------------------------------

#define NN 5000
#define WPR 157      // ceil(5000/32) words per bitmask row
#define WPRP 160     // padded words per row
#define DOUT 16
#define NCLS 100

__device__ unsigned g_bits[3][NN * WPRP];   // per-meta-path adjacency bitmasks
__device__ unsigned g_union[NN * WPRP];     // union pattern
__device__ float    g_dinv[3][NN];          // D^{-1/2} per meta-path (incl. self loop)
__device__ float    g_dinvu[NN];            // D^{-1/2} for union pattern
__device__ float    g_XWs[3][NN * DOUT];    // dinv[k][i] * (features @ W_gnn[k])[i]
__device__ float    g_fs[NN * DOUT];        // dinvu[i] * f_meta[i]
__device__ float    g_atta[NN * 4];         // a[i,k] (padded stride 4)
__device__ float    g_attb[NN * 4];         // b[j,k]

// ---------------------------------------------------------------------------
// K1: one streaming pass over adj (300 MB) -> bitmasks (3), union, degrees.
// ---------------------------------------------------------------------------
__global__ void k_prep(const float* __restrict__ adj) {
    int i = blockIdx.x;
    int t = threadIdx.x;                       // 256 threads
    __shared__ unsigned s_b[3][WPRP];
    __shared__ int s_cnt[4];
    if (t < 4) s_cnt[t] = 0;
    for (int x = t; x < 3 * WPRP; x += 256) ((unsigned*)s_b)[x] = 0;
    __syncthreads();

    #pragma unroll
    for (int k = 0; k < 3; k++) {
        const float4* rp = (const float4*)(adj + ((size_t)k * NN + i) * NN);
        float4 v[5];
        #pragma unroll
        for (int u = 0; u < 5; u++) {
            int q = t + 256 * u;
            if (q < 1250) v[u] = __ldcs(rp + q);
            else          v[u] = make_float4(0.f, 0.f, 0.f, 0.f);
        }
        #pragma unroll
        for (int u = 0; u < 5; u++) {
            int q = t + 256 * u;
            unsigned nb = (v[u].x != 0.f ? 1u : 0u) | (v[u].y != 0.f ? 2u : 0u) |
                          (v[u].z != 0.f ? 4u : 0u) | (v[u].w != 0.f ? 8u : 0u);
            if (nb && q < 1250) atomicOr(&s_b[k][q >> 3], nb << ((q & 7) * 4));
        }
    }
    __syncthreads();

    if (t < WPR) {
        unsigned b0 = s_b[0][t], b1 = s_b[1][t], b2 = s_b[2][t];
        unsigned u = b0 | b1 | b2;
        g_bits[0][i * WPRP + t] = b0;
        g_bits[1][i * WPRP + t] = b1;
        g_bits[2][i * WPRP + t] = b2;
        g_union[i * WPRP + t] = u;
        if (b0) atomicAdd(&s_cnt[0], __popc(b0));
        if (b1) atomicAdd(&s_cnt[1], __popc(b1));
        if (b2) atomicAdd(&s_cnt[2], __popc(b2));
        if (u)  atomicAdd(&s_cnt[3], __popc(u));
    }
    __syncthreads();
    if (t == 0) {
        g_dinv[0][i] = rsqrtf((float)(s_cnt[0] + 1));
        g_dinv[1][i] = rsqrtf((float)(s_cnt[1] + 1));
        g_dinv[2][i] = rsqrtf((float)(s_cnt[2] + 1));
        g_dinvu[i]   = rsqrtf((float)(s_cnt[3] + 1));
    }
}

// ---------------------------------------------------------------------------
// K2: XWs[k][i] = dinv[k][i] * (features[i] @ W_gnn[k]).  Register tile:
// 4 rows/thread share each W load; features staged in smem (float4 reads).
// ---------------------------------------------------------------------------
__global__ void k_xw(const float* __restrict__ feat, const float* __restrict__ W) {
    __shared__ float sf[16 * 512];             // 32 KB
    int i0 = blockIdx.x * 16;
    for (int x = threadIdx.x; x < 16 * 128; x += 192) {
        int r = x >> 7, c = x & 127;
        int gi = i0 + r;
        float4 v = make_float4(0.f, 0.f, 0.f, 0.f);
        if (gi < NN) v = ((const float4*)feat)[(size_t)gi * 128 + c];
        ((float4*)sf)[x] = v;
    }
    __syncthreads();

    int t = threadIdx.x;
    int o = t & 15;
    int k = (t >> 4) % 3;
    int rq = t / 48;                           // 0..3
    const float* wp = W + k * (512 * 16) + o;
    const float* f0 = sf + (rq * 4 + 0) * 512;
    const float* f1 = f0 + 512;
    const float* f2 = f1 + 512;
    const float* f3 = f2 + 512;
    float a0 = 0.f, a1 = 0.f, a2 = 0.f, a3 = 0.f;
    #pragma unroll 4
    for (int d = 0; d < 512; d += 4) {
        float w0 = wp[(d + 0) * 16];
        float w1 = wp[(d + 1) * 16];
        float w2 = wp[(d + 2) * 16];
        float w3 = wp[(d + 3) * 16];
        float4 x0 = *(const float4*)(f0 + d);
        float4 x1 = *(const float4*)(f1 + d);
        float4 x2 = *(const float4*)(f2 + d);
        float4 x3 = *(const float4*)(f3 + d);
        a0 = fmaf(x0.x, w0, fmaf(x0.y, w1, fmaf(x0.z, w2, fmaf(x0.w, w3, a0))));
        a1 = fmaf(x1.x, w0, fmaf(x1.y, w1, fmaf(x1.z, w2, fmaf(x1.w, w3, a1))));
        a2 = fmaf(x2.x, w0, fmaf(x2.y, w1, fmaf(x2.z, w2, fmaf(x2.w, w3, a2))));
        a3 = fmaf(x3.x, w0, fmaf(x3.y, w1, fmaf(x3.z, w2, fmaf(x3.w, w3, a3))));
    }
    int gi = i0 + rq * 4;
    if (gi + 0 < NN) g_XWs[k][(gi + 0) * DOUT + o] = a0 * g_dinv[k][gi + 0];
    if (gi + 1 < NN) g_XWs[k][(gi + 1) * DOUT + o] = a1 * g_dinv[k][gi + 1];
    if (gi + 2 < NN) g_XWs[k][(gi + 2) * DOUT + o] = a2 * g_dinv[k][gi + 2];
    if (gi + 3 < NN) g_XWs[k][(gi + 3) * DOUT + o] = a3 * g_dinv[k][gi + 3];
}

// ---------------------------------------------------------------------------
// Deterministic nonzero-list build within a 128-thread group.
// lt in [0,128). Returns count via *s_n.  All __syncthreads are block-wide:
// every group executes the identical sequence.
// ---------------------------------------------------------------------------
__device__ __forceinline__ void build_list(const unsigned* __restrict__ src, int lt,
                                           unsigned* s_w, int* s_cntw, int* s_base,
                                           int* s_list, int* s_n) {
    for (int w = lt; w < WPRP; w += 128) {
        unsigned m = (w < WPR) ? src[w] : 0u;
        s_w[w] = m;
        s_cntw[w] = __popc(m);
    }
    __syncthreads();
    if (lt < 32) {
        int run = 0;
        #pragma unroll
        for (int g = 0; g < 5; g++) {
            int w = g * 32 + lt;
            int c = s_cntw[w];
            int x = c;
            #pragma unroll
            for (int off = 1; off < 32; off <<= 1) {
                int y = __shfl_up_sync(0xffffffffu, x, off);
                if (lt >= off) x += y;
            }
            s_base[w] = run + x - c;
            run += __shfl_sync(0xffffffffu, x, 31);
        }
        if (lt == 0) *s_n = run;
    }
    __syncthreads();
    for (int w = lt; w < WPR; w += 128) {
        unsigned m = s_w[w];
        int base = s_base[w];
        int jb = w * 32;
        while (m) {
            int b = __ffs(m) - 1; m &= m - 1;
            s_list[base++] = jb + b;
        }
    }
    __syncthreads();
}

// Unroll-4 gather-accumulate over a list (stride 8 within a group).
__device__ __forceinline__ float gather_sum(const float* __restrict__ X,
                                            const int* __restrict__ list,
                                            int E, int sub, int dim) {
    float acc = 0.f;
    int e = sub;
    for (; e + 24 < E; e += 32) {
        int j0 = list[e], j1 = list[e + 8], j2 = list[e + 16], j3 = list[e + 24];
        float x0 = X[j0 * DOUT + dim];
        float x1 = X[j1 * DOUT + dim];
        float x2 = X[j2 * DOUT + dim];
        float x3 = X[j3 * DOUT + dim];
        acc += (x0 + x1) + (x2 + x3);
    }
    for (; e < E; e += 8) acc += X[list[e] * DOUT + dim];
    return acc;
}

// ---------------------------------------------------------------------------
// K3: 3 meta-path GCN convs in parallel (warpgroup per k) + max -> f_meta,
// scaled f_s, attention projections. Block per row, 384 threads.
// ---------------------------------------------------------------------------
__global__ void k_hatt(const float* __restrict__ bgnn, const float* __restrict__ attw,
                       float* __restrict__ fmeta) {
    int i = blockIdx.x;
    int t = threadIdx.x;
    int k = t >> 7;               // warpgroup = meta-path
    int lt = t & 127;
    int lane = lt & 31, warp = lt >> 5;
    int dim = lt & 15, sub = lt >> 4;

    __shared__ unsigned s_w[3][WPRP];
    __shared__ int s_cntw[3][WPRP];
    __shared__ int s_base[3][WPRP];
    __shared__ int s_list[3][320];
    __shared__ int s_n[3];
    __shared__ float s_part[3][4][16];
    __shared__ float s_h[3][16];

    build_list(&g_bits[k][i * WPRP], lt, s_w[k], s_cntw[k], s_base[k],
               s_list[k], &s_n[k]);

    const float* Xs = g_XWs[k];
    float acc = gather_sum(Xs, s_list[k], s_n[k], sub, dim);

    acc += __shfl_xor_sync(0xffffffffu, acc, 16);
    if (lane < 16) s_part[k][warp][lane] = acc;
    __syncthreads();
    if (lt < 16) {
        float s = s_part[k][0][lt] + s_part[k][1][lt] +
                  s_part[k][2][lt] + s_part[k][3][lt];
        // h = di * (sum_j XWs[j] + XWs[i]) + b   (XWs pre-scaled by dinv)
        float di = g_dinv[k][i];
        s_h[k][lt] = fmaf(di, s + Xs[i * DOUT + lt], bgnn[k * 16 + lt]);
    }
    __syncthreads();

    if (t < 32) {
        float best = 0.f;
        if (t < 16) {
            best = fmaxf(s_h[0][t], fmaxf(s_h[1][t], s_h[2][t]));
            fmeta[i * DOUT + t] = best;
            g_fs[i * DOUT + t] = g_dinvu[i] * best;
        }
        #pragma unroll
        for (int kk = 0; kk < 3; kk++) {
            float va = (t < 16) ? best * attw[kk * 32 + t] : 0.f;
            float vb = (t < 16) ? best * attw[kk * 32 + 16 + t] : 0.f;
            #pragma unroll
            for (int off = 8; off >= 1; off >>= 1) {
                va += __shfl_xor_sync(0xffffffffu, va, off);
                vb += __shfl_xor_sync(0xffffffffu, vb, off);
            }
            if (t == 0) { g_atta[i * 4 + kk] = va; g_attb[i * 4 + kk] = vb; }
        }
    }
}

// ---------------------------------------------------------------------------
// K4: A_meta dense write (100 MB), fused attention softmax on union nonzeros.
// ---------------------------------------------------------------------------
__global__ void k_ameta(float* __restrict__ Am) {
    int tid = blockIdx.x * blockDim.x + threadIdx.x;
    if (tid >= NN * 1250) return;
    int i = tid / 1250, q = tid - i * 1250;
    int j0 = q * 4, w = j0 >> 5, sh = j0 & 31;
    unsigned uw = g_union[i * WPRP + w];
    float4 out = make_float4(0.f, 0.f, 0.f, 0.f);
    unsigned sub = (uw >> sh) & 0xFu;
    if (sub) {
        float4 A = *(const float4*)&g_atta[i * 4];
        unsigned m0 = g_bits[0][i * WPRP + w] >> sh;
        unsigned m1 = g_bits[1][i * WPRP + w] >> sh;
        unsigned m2 = g_bits[2][i * WPRP + w] >> sh;
        float v[4];
        #pragma unroll
        for (int c = 0; c < 4; c++) {
            float r = 0.f;
            if ((sub >> c) & 1u) {
                int j = j0 + c;
                float4 B = *(const float4*)&g_attb[j * 4];
                float s0 = __expf(fmaxf(A.x + B.x, 0.f));
                float s1 = __expf(fmaxf(A.y + B.y, 0.f));
                float s2 = __expf(fmaxf(A.z + B.z, 0.f));
                float num = (((m0 >> c) & 1u) ? s0 : 0.f) +
                            (((m1 >> c) & 1u) ? s1 : 0.f) +
                            (((m2 >> c) & 1u) ? s2 : 0.f);
                r = __fdividef(num, s0 + s1 + s2);
            }
            v[c] = r;
        }
        out = make_float4(v[0], v[1], v[2], v[3]);
    }
    __stcs(((float4*)Am) + tid, out);
}

// ---------------------------------------------------------------------------
// K5: t = norm_meta @ f_meta (union SpMM via pre-scaled g_fs), fused with
// predictions = t @ W_final + b_final.  Block per row, 128 threads.
// ---------------------------------------------------------------------------
__global__ void k_tpred(const float* __restrict__ Wf, const float* __restrict__ bf,
                        float* __restrict__ pred) {
    int i = blockIdx.x;
    int t = threadIdx.x;
    int lane = t & 31, warp = t >> 5;
    int dim = t & 15, sub = t >> 4;
    __shared__ unsigned s_w[WPRP];
    __shared__ int s_cntw[WPRP];
    __shared__ int s_base[WPRP];
    __shared__ int s_list[384];
    __shared__ int s_n;
    __shared__ float s_part[4][16];
    __shared__ float s_t[16];

    build_list(g_union + i * WPRP, t, s_w, s_cntw, s_base, s_list, &s_n);

    float acc = gather_sum(g_fs, s_list, s_n, sub, dim);

    acc += __shfl_xor_sync(0xffffffffu, acc, 16);
    if (lane < 16) s_part[warp][lane] = acc;
    __syncthreads();
    if (t < 16) {
        float di = g_dinvu[i];
        // t_i = di * (sum_j fs[j] + fs[i])   (fs pre-scaled by dinvu)
        s_t[t] = di * (s_part[0][t] + s_part[1][t] + s_part[2][t] + s_part[3][t]
                       + g_fs[i * DOUT + t]);
    }
    __syncthreads();
    if (t < NCLS) {
        float p = bf[t];
        #pragma unroll
        for (int o = 0; o < DOUT; o++)
            p = fmaf(s_t[o], Wf[o * NCLS + t], p);
        pred[i * NCLS + t] = p;
    }
}

// ---------------------------------------------------------------------------
extern "C" void kernel_launch(void* const* d_in, const int* in_sizes, int n_in,
                              void* d_out, int out_size) {
    const float* features = (const float*)d_in[0];
    const float* adj      = (const float*)d_in[1];
    const float* W_gnn    = (const float*)d_in[2];
    const float* b_gnn    = (const float*)d_in[3];
    const float* att_w    = (const float*)d_in[4];
    const float* W_final  = (const float*)d_in[5];
    const float* b_final  = (const float*)d_in[6];

    float* out   = (float*)d_out;
    float* fmeta = out;                                        // [5000,16]
    float* Ameta = out + (size_t)NN * DOUT;                    // [5000,5000]
    float* pred  = out + (size_t)NN * DOUT + (size_t)NN * NN;  // [5000,100]

    k_prep<<<NN, 256>>>(adj);
    k_xw<<<(NN + 15) / 16, 192>>>(features, W_gnn);
    k_hatt<<<NN, 384>>>(b_gnn, att_w, fmeta);
    k_ameta<<<(NN * 1250 + 255) / 256, 256>>>(Ameta);
    k_tpred<<<NN, 128>>>(W_final, b_final, pred);
}